// round 9
// baseline (speedup 1.0000x reference)
#include <cuda_runtime.h>
#include <cuda_fp16.h>
#include <stdint.h>

#define HD    128
#define BB    64
#define LQ    64
#define LDOC  4096
#define NTILE 32               // 4096/128 doc tiles per batch
#define LN_EPS 1e-5f
#define NEGV  -1e30f

// ---------------- scratch (__device__ globals; no cudaMalloc) --------------
__device__ __half g_wt[4][HD * HD];                 // transposed fp16 weights
__device__ __half g_qv[(size_t)BB * LQ * HD];       // 1 MB, stored SWIZZLED
__device__ float  g_pmax[(size_t)BB * NTILE * LQ];  // 512 KB

// ---------------- helpers ---------------------------------------------------
__device__ __forceinline__ uint32_t smem_u32(const void* p) {
    uint32_t a;
    asm("{ .reg .u64 t; cvta.to.shared.u64 t, %1; cvt.u32.u64 %0, t; }"
        : "=r"(a) : "l"(p));
    return a;
}

__device__ __forceinline__ void ldsm_x4(uint32_t& r0, uint32_t& r1,
                                        uint32_t& r2, uint32_t& r3, uint32_t a) {
    asm volatile("ldmatrix.sync.aligned.m8n8.x4.shared.b16 {%0,%1,%2,%3}, [%4];"
                 : "=r"(r0), "=r"(r1), "=r"(r2), "=r"(r3) : "r"(a));
}

__device__ __forceinline__ void mma16816(float* c,
                                         uint32_t a0, uint32_t a1, uint32_t a2,
                                         uint32_t a3, uint32_t b0, uint32_t b1) {
    asm volatile(
        "mma.sync.aligned.m16n8k16.row.col.f32.f16.f16.f32 "
        "{%0,%1,%2,%3}, {%4,%5,%6,%7}, {%8,%9}, {%0,%1,%2,%3};"
        : "+f"(c[0]), "+f"(c[1]), "+f"(c[2]), "+f"(c[3])
        : "r"(a0), "r"(a1), "r"(a2), "r"(a3), "r"(b0), "r"(b1));
}

__device__ __forceinline__ uint32_t pack2(float a, float b) {
    __half2 h = __floats2half2_rn(a, b);
    return *(uint32_t*)&h;
}

// swizzled smem offset for (row, 16B-chunk) in a [rows][256B] fp16 tile
__device__ __forceinline__ uint32_t swz(int row, int chunk) {
    return (uint32_t)(row * 256 + ((chunk ^ (row & 7)) * 16));
}

// ---------------- prep: transpose + fp16 convert of the 4 weights ----------
__global__ void prep_kernel(const float* __restrict__ dW1,
                            const float* __restrict__ dW2,
                            const float* __restrict__ qW1,
                            const float* __restrict__ qW2) {
    int i = blockIdx.x * blockDim.x + threadIdx.x;   // 65536 total
    const float* Ws[4] = {dW1, dW2, qW1, qW2};
    int mat = i >> 14, r = i & 16383, j = r >> 7, k = r & 127;
    g_wt[mat][j * HD + k] = __float2half_rn(Ws[mat][k * HD + j]);
}

// ---------------- fused encode (+maxsim for docs) --------------------------
// 128 threads = 4 warps, M=32 token rows per warp. Activations live in
// registers between layers (C-fragment == A-fragment identity).
#define ESM_X   0
#define ESM_WA  32768
#define ESM_WB  65536
#define ESM_P   98304
#define ESM_RED 100352
#define ESM_TOTAL 101376

// acc initialized with bias; A from SMEM tile Xb (layer 1)
__device__ __forceinline__ void mma_A_smem(float (&acc)[2][16][4],
                                           uint32_t Xb, uint32_t Wb,
                                           int lane, int wrow) {
    const int arow  = wrow + (lane & 7) + ((lane >> 3) & 1) * 8;
    const int akc   = (lane >> 4) & 1;
    const int brow0 = (lane & 7) + ((lane >> 4) & 1) * 8;
    const int bkc   = (lane >> 3) & 1;
#pragma unroll
    for (int kk = 0; kk < 8; kk++) {
        uint32_t a0[4], a1[4];
        ldsm_x4(a0[0], a0[1], a0[2], a0[3], Xb + swz(arow,      kk * 2 + akc));
        ldsm_x4(a1[0], a1[1], a1[2], a1[3], Xb + swz(arow + 16, kk * 2 + akc));
#pragma unroll
        for (int nt2 = 0; nt2 < 8; nt2++) {
            uint32_t b0, b1, b2, b3;
            ldsm_x4(b0, b1, b2, b3, Wb + swz(nt2 * 16 + brow0, kk * 2 + bkc));
            mma16816(acc[0][2 * nt2],     a0[0], a0[1], a0[2], a0[3], b0, b1);
            mma16816(acc[0][2 * nt2 + 1], a0[0], a0[1], a0[2], a0[3], b2, b3);
            mma16816(acc[1][2 * nt2],     a1[0], a1[1], a1[2], a1[3], b0, b1);
            mma16816(acc[1][2 * nt2 + 1], a1[0], a1[1], a1[2], a1[3], b2, b3);
        }
    }
}

// acc initialized with bias; A from register fragments ah
__device__ __forceinline__ void mma_A_reg(float (&acc)[2][16][4],
                                          const uint32_t (&ah)[2][8][4],
                                          uint32_t Wb, int lane) {
    const int brow0 = (lane & 7) + ((lane >> 4) & 1) * 8;
    const int bkc   = (lane >> 3) & 1;
#pragma unroll
    for (int kk = 0; kk < 8; kk++) {
#pragma unroll
        for (int nt2 = 0; nt2 < 8; nt2++) {
            uint32_t b0, b1, b2, b3;
            ldsm_x4(b0, b1, b2, b3, Wb + swz(nt2 * 16 + brow0, kk * 2 + bkc));
            mma16816(acc[0][2 * nt2],     ah[0][kk][0], ah[0][kk][1],
                     ah[0][kk][2], ah[0][kk][3], b0, b1);
            mma16816(acc[0][2 * nt2 + 1], ah[0][kk][0], ah[0][kk][1],
                     ah[0][kk][2], ah[0][kk][3], b2, b3);
            mma16816(acc[1][2 * nt2],     ah[1][kk][0], ah[1][kk][1],
                     ah[1][kk][2], ah[1][kk][3], b0, b1);
            mma16816(acc[1][2 * nt2 + 1], ah[1][kk][0], ah[1][kk][1],
                     ah[1][kk][2], ah[1][kk][3], b2, b3);
        }
    }
}

__device__ __forceinline__ void init_bias(float (&acc)[2][16][4],
                                          const float* __restrict__ sB, int q4) {
#pragma unroll
    for (int nt = 0; nt < 16; nt++) {
        const float2 bc = *(const float2*)(sB + nt * 8 + 2 * q4);
#pragma unroll
        for (int mt = 0; mt < 2; mt++) {
            acc[mt][nt][0] = bc.x; acc[mt][nt][1] = bc.y;
            acc[mt][nt][2] = bc.x; acc[mt][nt][3] = bc.y;
        }
    }
}

// ReLU + LayerNorm (+opt mask) -> fp16 A fragments (and optionally SMEM X)
__device__ __forceinline__ void epilogue(float (&acc)[2][16][4],
                                         uint32_t (&ah)[2][8][4],
                                         const float* __restrict__ sLW,
                                         const float* __restrict__ sLB,
                                         int lane, int wrow,
                                         const int* __restrict__ mrow,
                                         char* __restrict__ smem, int store_x) {
    const int g = lane >> 2, q4 = lane & 3;
#pragma unroll
    for (int mt = 0; mt < 2; mt++) {
        float s0 = 0.f, ss0 = 0.f, s1 = 0.f, ss1 = 0.f;
#pragma unroll
        for (int nt = 0; nt < 16; nt++) {
            float v0 = fmaxf(acc[mt][nt][0], 0.f);
            float v1 = fmaxf(acc[mt][nt][1], 0.f);
            float v2 = fmaxf(acc[mt][nt][2], 0.f);
            float v3 = fmaxf(acc[mt][nt][3], 0.f);
            acc[mt][nt][0] = v0; acc[mt][nt][1] = v1;
            acc[mt][nt][2] = v2; acc[mt][nt][3] = v3;
            s0 += v0 + v1; ss0 += v0 * v0 + v1 * v1;
            s1 += v2 + v3; ss1 += v2 * v2 + v3 * v3;
        }
#pragma unroll
        for (int o = 1; o <= 2; o <<= 1) {
            s0  += __shfl_xor_sync(0xffffffffu, s0,  o);
            ss0 += __shfl_xor_sync(0xffffffffu, ss0, o);
            s1  += __shfl_xor_sync(0xffffffffu, s1,  o);
            ss1 += __shfl_xor_sync(0xffffffffu, ss1, o);
        }
        const int r0 = wrow + mt * 16 + g, r1 = r0 + 8;
        const float mean0 = s0 * (1.0f / HD);
        const float mean1 = s1 * (1.0f / HD);
        const float rstd0 = rsqrtf(ss0 * (1.0f / HD) - mean0 * mean0 + LN_EPS);
        const float rstd1 = rsqrtf(ss1 * (1.0f / HD) - mean1 * mean1 + LN_EPS);
        const float mv0 = mrow ? (float)mrow[r0] : 1.0f;
        const float mv1 = mrow ? (float)mrow[r1] : 1.0f;
#pragma unroll
        for (int kk = 0; kk < 8; kk++) {
            const int nta = 2 * kk, ntb = 2 * kk + 1;
            const float2 lwa = *(const float2*)(sLW + nta * 8 + 2 * q4);
            const float2 lba = *(const float2*)(sLB + nta * 8 + 2 * q4);
            const float2 lwb = *(const float2*)(sLW + ntb * 8 + 2 * q4);
            const float2 lbb = *(const float2*)(sLB + ntb * 8 + 2 * q4);
            float y00 = ((acc[mt][nta][0] - mean0) * rstd0 * lwa.x + lba.x) * mv0;
            float y01 = ((acc[mt][nta][1] - mean0) * rstd0 * lwa.y + lba.y) * mv0;
            float y10 = ((acc[mt][nta][2] - mean1) * rstd1 * lwa.x + lba.x) * mv1;
            float y11 = ((acc[mt][nta][3] - mean1) * rstd1 * lwa.y + lba.y) * mv1;
            float y20 = ((acc[mt][ntb][0] - mean0) * rstd0 * lwb.x + lbb.x) * mv0;
            float y21 = ((acc[mt][ntb][1] - mean0) * rstd0 * lwb.y + lbb.y) * mv0;
            float y30 = ((acc[mt][ntb][2] - mean1) * rstd1 * lwb.x + lbb.x) * mv1;
            float y31 = ((acc[mt][ntb][3] - mean1) * rstd1 * lwb.y + lbb.y) * mv1;
            ah[mt][kk][0] = pack2(y00, y01);
            ah[mt][kk][1] = pack2(y10, y11);
            ah[mt][kk][2] = pack2(y20, y21);
            ah[mt][kk][3] = pack2(y30, y31);
            if (store_x) {
                *(uint32_t*)(smem + ESM_X + swz(r0, nta) + 4 * q4) = ah[mt][kk][0];
                *(uint32_t*)(smem + ESM_X + swz(r1, nta) + 4 * q4) = ah[mt][kk][1];
                *(uint32_t*)(smem + ESM_X + swz(r0, ntb) + 4 * q4) = ah[mt][kk][2];
                *(uint32_t*)(smem + ESM_X + swz(r1, ntb) + 4 * q4) = ah[mt][kk][3];
            }
        }
    }
}

template <int ISQ>
__global__ __launch_bounds__(128, 2)
void encode_fused(const int* __restrict__ ids, const int* __restrict__ mask,
                  const float* __restrict__ emb,
                  const float* __restrict__ b1, const float* __restrict__ b2,
                  const float* __restrict__ lnw, const float* __restrict__ lnb,
                  const int* __restrict__ dmask, int mat0)
{
    extern __shared__ __align__(16) char smem[];
    const int tid = threadIdx.x, wid = tid >> 5, lane = tid & 31;
    const uint32_t sb = smem_u32(smem);
    float* sP = (float*)(smem + ESM_P);

    sP[tid]       = b1[tid];
    sP[128 + tid] = b2[tid];
    sP[256 + tid] = lnw[tid];
    sP[384 + tid] = lnb[tid];

    // W1 -> WA, W2 -> WB (swizzled)
    {
        const uint4* w1 = (const uint4*)g_wt[mat0];
        const uint4* w2 = (const uint4*)g_wt[mat0 + 1];
#pragma unroll
        for (int i = 0; i < 16; i++) {
            int idx = tid + i * 128;       // 2048 chunks
            int r = idx >> 4, c = idx & 15;
            *(uint4*)(smem + ESM_WA + swz(r, c)) = w1[idx];
            *(uint4*)(smem + ESM_WB + swz(r, c)) = w2[idx];
        }
    }

    // embedding gather: 1 thread per token (warp writes only its own rows)
    {
        const int id = ids[(size_t)blockIdx.x * 128 + tid];
        const float4* er = (const float4*)(emb + (size_t)id * HD);
#pragma unroll
        for (int c = 0; c < 16; c++) {
            float4 fa = er[2 * c], fb = er[2 * c + 1];
            *(uint4*)(smem + ESM_X + swz(tid, c)) =
                make_uint4(pack2(fa.x, fa.y), pack2(fa.z, fa.w),
                           pack2(fb.x, fb.y), pack2(fb.z, fb.w));
        }
    }
    __syncthreads();

    const int wrow = wid * 32;
    float acc[2][16][4];
    uint32_t ah[2][8][4];

    // ---- layer 1 ----
    init_bias(acc, sP, lane & 3);
    mma_A_smem(acc, sb + ESM_X, sb + ESM_WA, lane, wrow);
    epilogue(acc, ah, sP + 256, sP + 384, lane, wrow, nullptr, smem, 0);
    __syncthreads();   // all warps done reading WA (W1)

    if (!ISQ) {
        // stage this batch's query tile (already swizzled in g_qv) into WA
        const int b = blockIdx.x >> 5;
        const uint4* qs = (const uint4*)(g_qv + (size_t)b * LQ * HD);
#pragma unroll
        for (int i = 0; i < 8; i++)
            ((uint4*)(smem + ESM_WA))[tid + i * 128] = qs[tid + i * 128];
    }
    __syncthreads();   // Q staged before sim reads it

    // ---- layer 2 (A from registers) ----
    init_bias(acc, sP + 128, lane & 3);
    mma_A_reg(acc, ah, sb + ESM_WB, lane);
    epilogue(acc, ah, sP + 256, sP + 384, lane, wrow,
             ISQ ? (mask + (size_t)blockIdx.x * 128) : nullptr, smem, ISQ);

    if (ISQ) {
        __syncthreads();
        uint4* gdst = (uint4*)g_qv + (size_t)blockIdx.x * 2048;
#pragma unroll
        for (int i = 0; i < 16; i++)
            gdst[tid + i * 128] = ((const uint4*)(smem + ESM_X))[tid + i * 128];
        return;
    }

    // ---- fused maxsim: D[128 docs] x Q[64 queries], K=128 (A from regs) ----
    float sa[2][8][4];
#pragma unroll
    for (int mt = 0; mt < 2; mt++)
#pragma unroll
        for (int nt = 0; nt < 8; nt++) {
            sa[mt][nt][0] = 0.f; sa[mt][nt][1] = 0.f;
            sa[mt][nt][2] = 0.f; sa[mt][nt][3] = 0.f;
        }
    {
        const int brow0 = (lane & 7) + ((lane >> 4) & 1) * 8;
        const int bkc   = (lane >> 3) & 1;
#pragma unroll
        for (int kk = 0; kk < 8; kk++) {
#pragma unroll
            for (int nt2 = 0; nt2 < 4; nt2++) {
                uint32_t b0, b1, b2, b3;
                ldsm_x4(b0, b1, b2, b3,
                        sb + ESM_WA + swz(nt2 * 16 + brow0, kk * 2 + bkc));
                mma16816(sa[0][2 * nt2],     ah[0][kk][0], ah[0][kk][1],
                         ah[0][kk][2], ah[0][kk][3], b0, b1);
                mma16816(sa[0][2 * nt2 + 1], ah[0][kk][0], ah[0][kk][1],
                         ah[0][kk][2], ah[0][kk][3], b2, b3);
                mma16816(sa[1][2 * nt2],     ah[1][kk][0], ah[1][kk][1],
                         ah[1][kk][2], ah[1][kk][3], b0, b1);
                mma16816(sa[1][2 * nt2 + 1], ah[1][kk][0], ah[1][kk][1],
                         ah[1][kk][2], ah[1][kk][3], b2, b3);
            }
        }
    }

    // penalties + max over this warp's 32 doc rows
    const int g = lane >> 2;
    int r4[4] = {wrow + g, wrow + g + 8, wrow + 16 + g, wrow + 24 + g};
    float p[4];
#pragma unroll
    for (int j = 0; j < 4; j++)
        p[j] = (1.0f - (float)dmask[(size_t)blockIdx.x * 128 + r4[j]]) * NEGV;

    float* red = (float*)(smem + ESM_RED);
#pragma unroll
    for (int nt = 0; nt < 8; nt++) {
        float v0 = -3.0e38f, v1 = -3.0e38f;
#pragma unroll
        for (int j = 0; j < 4; j++) {
            const int mt = j >> 1, h = j & 1;
            v0 = fmaxf(v0, sa[mt][nt][2 * h]     + p[j]);
            v1 = fmaxf(v1, sa[mt][nt][2 * h + 1] + p[j]);
        }
#pragma unroll
        for (int o = 4; o <= 16; o <<= 1) {
            v0 = fmaxf(v0, __shfl_xor_sync(0xffffffffu, v0, o));
            v1 = fmaxf(v1, __shfl_xor_sync(0xffffffffu, v1, o));
        }
        if (lane < 4)
            *(float2*)(red + wid * 64 + nt * 8 + 2 * lane) = make_float2(v0, v1);
    }
    __syncthreads();
    if (tid < 64) {
        float m = red[tid];
#pragma unroll
        for (int w = 1; w < 4; w++) m = fmaxf(m, red[w * 64 + tid]);
        g_pmax[(size_t)blockIdx.x * 64 + tid] = m;
    }
}

// ---------------- final: max over tiles, sum over queries ------------------
__global__ void final_k(float* __restrict__ out)
{
    const int b = blockIdx.x, tid = threadIdx.x;    // 256 threads
    const int q = tid & 63, part = tid >> 6;        // 4 parts x 8 tiles
    float m = -3.0e38f;
#pragma unroll
    for (int t = 0; t < 8; t++)
        m = fmaxf(m, g_pmax[(size_t)b * (NTILE * LQ) + (part * 8 + t) * LQ + q]);
    __shared__ float red[256];
    red[tid] = m;
    __syncthreads();
    if (tid < 64) {
        float s = fmaxf(fmaxf(red[tid], red[tid + 64]),
                        fmaxf(red[tid + 128], red[tid + 192]));
#pragma unroll
        for (int o = 16; o > 0; o >>= 1)
            s += __shfl_xor_sync(0xffffffffu, s, o);
        if ((tid & 31) == 0) red[tid >> 5] = s;
    }
    __syncthreads();
    if (tid == 0) out[b] = red[0] + red[1];
}

// ---------------- launch ---------------------------------------------------
extern "C" void kernel_launch(void* const* d_in, const int* in_sizes, int n_in,
                              void* d_out, int out_size)
{
    const int*   qids  = (const int*)d_in[0];
    const int*   dids  = (const int*)d_in[1];
    const int*   qmask = (const int*)d_in[2];
    const int*   dmask = (const int*)d_in[3];
    const float* q_emb = (const float*)d_in[4];
    const float* qW1   = (const float*)d_in[5];
    const float* qb1   = (const float*)d_in[6];
    const float* qW2   = (const float*)d_in[7];
    const float* qb2   = (const float*)d_in[8];
    const float* q_lnw = (const float*)d_in[9];
    const float* q_lnb = (const float*)d_in[10];
    const float* d_emb = (const float*)d_in[11];
    const float* dW1   = (const float*)d_in[12];
    const float* db1   = (const float*)d_in[13];
    const float* dW2   = (const float*)d_in[14];
    const float* db2   = (const float*)d_in[15];
    const float* d_lnw = (const float*)d_in[16];
    const float* d_lnb = (const float*)d_in[17];
    float* out = (float*)d_out;

    cudaFuncSetAttribute(encode_fused<0>,
        cudaFuncAttributeMaxDynamicSharedMemorySize, ESM_TOTAL);
    cudaFuncSetAttribute(encode_fused<1>,
        cudaFuncAttributeMaxDynamicSharedMemorySize, ESM_TOTAL);

    prep_kernel<<<256, 256>>>(dW1, dW2, qW1, qW2);

    // queries first (writes g_qv, swizzled)
    encode_fused<1><<<(BB * LQ) / 128, 128, ESM_TOTAL>>>(
        qids, qmask, q_emb, qb1, qb2, q_lnw, q_lnb, dmask, 2);
    // docs with fused maxsim (reads g_qv, writes g_pmax)
    encode_fused<0><<<(BB * LDOC) / 128, 128, ESM_TOTAL>>>(
        dids, dmask, d_emb, db1, db2, d_lnw, d_lnb, dmask, 0);

    final_k<<<BB, 256>>>(out);
}

// round 10
// speedup vs baseline: 1.3913x; 1.3913x over previous
#include <cuda_runtime.h>
#include <cuda_fp16.h>
#include <stdint.h>

#define HD    128
#define BB    64
#define LQ    64
#define LDOC  4096
#define NTILE 32               // 4096/128 doc tiles per batch
#define LN_EPS 1e-5f
#define NEGV  -1e30f

// ---------------- scratch (__device__ globals; no cudaMalloc) --------------
__device__ __half g_wt[4][HD * HD];                 // transposed fp16 weights
__device__ __half g_qv[(size_t)BB * LQ * HD];       // 1 MB, stored SWIZZLED
__device__ float  g_pmax[(size_t)BB * NTILE * LQ];  // 512 KB

// ---------------- helpers ---------------------------------------------------
__device__ __forceinline__ uint32_t smem_u32(const void* p) {
    uint32_t a;
    asm("{ .reg .u64 t; cvta.to.shared.u64 t, %1; cvt.u32.u64 %0, t; }"
        : "=r"(a) : "l"(p));
    return a;
}

__device__ __forceinline__ void ldsm_x4(uint32_t& r0, uint32_t& r1,
                                        uint32_t& r2, uint32_t& r3, uint32_t a) {
    asm volatile("ldmatrix.sync.aligned.m8n8.x4.shared.b16 {%0,%1,%2,%3}, [%4];"
                 : "=r"(r0), "=r"(r1), "=r"(r2), "=r"(r3) : "r"(a));
}

__device__ __forceinline__ void mma16816(float* c,
                                         uint32_t a0, uint32_t a1, uint32_t a2,
                                         uint32_t a3, uint32_t b0, uint32_t b1) {
    asm volatile(
        "mma.sync.aligned.m16n8k16.row.col.f32.f16.f16.f32 "
        "{%0,%1,%2,%3}, {%4,%5,%6,%7}, {%8,%9}, {%0,%1,%2,%3};"
        : "+f"(c[0]), "+f"(c[1]), "+f"(c[2]), "+f"(c[3])
        : "r"(a0), "r"(a1), "r"(a2), "r"(a3), "r"(b0), "r"(b1));
}

__device__ __forceinline__ uint32_t pack2(float a, float b) {
    __half2 h = __floats2half2_rn(a, b);
    return *(uint32_t*)&h;
}

// swizzled smem offset for (row, 16B-chunk) in a [rows][256B] fp16 tile
__device__ __forceinline__ uint32_t swz(int row, int chunk) {
    return (uint32_t)(row * 256 + ((chunk ^ (row & 7)) * 16));
}

// ---------------- prep: transpose + fp16 convert of the 4 weights ----------
__global__ void prep_kernel(const float* __restrict__ dW1,
                            const float* __restrict__ dW2,
                            const float* __restrict__ qW1,
                            const float* __restrict__ qW2) {
    int i = blockIdx.x * blockDim.x + threadIdx.x;   // 65536 total
    const float* Ws[4] = {dW1, dW2, qW1, qW2};
    int mat = i >> 14, r = i & 16383, j = r >> 7, k = r & 127;
    g_wt[mat][j * HD + k] = __float2half_rn(Ws[mat][k * HD + j]);
}

// ---------------- fused encode (+maxsim for docs) --------------------------
// 128 threads = 4 warps, M=32 token rows per warp.
#define ESM_X   0
#define ESM_WA  32768
#define ESM_WB  65536
#define ESM_P   98304
#define ESM_RED 100352
#define ESM_TOTAL 101376

__device__ __forceinline__ void init_bias(float (&acc)[2][16][4],
                                          const float* __restrict__ sB, int q4) {
#pragma unroll
    for (int nt = 0; nt < 16; nt++) {
        const float2 bc = *(const float2*)(sB + nt * 8 + 2 * q4);
#pragma unroll
        for (int mt = 0; mt < 2; mt++) {
            acc[mt][nt][0] = bc.x; acc[mt][nt][1] = bc.y;
            acc[mt][nt][2] = bc.x; acc[mt][nt][3] = bc.y;
        }
    }
}

// A from SMEM tile Xb, B double-buffered from Wb
__device__ __forceinline__ void mma_A_smem(float (&acc)[2][16][4],
                                           uint32_t Xb, uint32_t Wb,
                                           int lane, int wrow) {
    const int arow  = wrow + (lane & 7) + ((lane >> 3) & 1) * 8;
    const int akc   = (lane >> 4) & 1;
    const int brow0 = (lane & 7) + ((lane >> 4) & 1) * 8;
    const int bkc   = (lane >> 3) & 1;
#pragma unroll
    for (int kk = 0; kk < 8; kk++) {
        uint32_t a0[4], a1[4];
        ldsm_x4(a0[0], a0[1], a0[2], a0[3], Xb + swz(arow,      kk * 2 + akc));
        ldsm_x4(a1[0], a1[1], a1[2], a1[3], Xb + swz(arow + 16, kk * 2 + akc));
        uint32_t bc_[2][4];
        ldsm_x4(bc_[0][0], bc_[0][1], bc_[0][2], bc_[0][3],
                Wb + swz(brow0, kk * 2 + bkc));
#pragma unroll
        for (int nt2 = 0; nt2 < 8; nt2++) {
            const int cur = nt2 & 1, nxt = cur ^ 1;
            if (nt2 < 7)
                ldsm_x4(bc_[nxt][0], bc_[nxt][1], bc_[nxt][2], bc_[nxt][3],
                        Wb + swz((nt2 + 1) * 16 + brow0, kk * 2 + bkc));
            mma16816(acc[0][2 * nt2],     a0[0], a0[1], a0[2], a0[3],
                     bc_[cur][0], bc_[cur][1]);
            mma16816(acc[0][2 * nt2 + 1], a0[0], a0[1], a0[2], a0[3],
                     bc_[cur][2], bc_[cur][3]);
            mma16816(acc[1][2 * nt2],     a1[0], a1[1], a1[2], a1[3],
                     bc_[cur][0], bc_[cur][1]);
            mma16816(acc[1][2 * nt2 + 1], a1[0], a1[1], a1[2], a1[3],
                     bc_[cur][2], bc_[cur][3]);
        }
    }
}

// ReLU + LayerNorm (+opt mask) -> fp16 A fragments ah, optionally also SMEM X
__device__ __forceinline__ void epilogue(float (&acc)[2][16][4],
                                         uint32_t (&ah)[2][8][4],
                                         const float* __restrict__ sLW,
                                         const float* __restrict__ sLB,
                                         int lane, int wrow,
                                         const int* __restrict__ mrow,
                                         char* __restrict__ smem, int store_x) {
    const int g = lane >> 2, q4 = lane & 3;
#pragma unroll
    for (int mt = 0; mt < 2; mt++) {
        float s0 = 0.f, ss0 = 0.f, s1 = 0.f, ss1 = 0.f;
#pragma unroll
        for (int nt = 0; nt < 16; nt++) {
            float v0 = fmaxf(acc[mt][nt][0], 0.f);
            float v1 = fmaxf(acc[mt][nt][1], 0.f);
            float v2 = fmaxf(acc[mt][nt][2], 0.f);
            float v3 = fmaxf(acc[mt][nt][3], 0.f);
            acc[mt][nt][0] = v0; acc[mt][nt][1] = v1;
            acc[mt][nt][2] = v2; acc[mt][nt][3] = v3;
            s0 += v0 + v1; ss0 += v0 * v0 + v1 * v1;
            s1 += v2 + v3; ss1 += v2 * v2 + v3 * v3;
        }
#pragma unroll
        for (int o = 1; o <= 2; o <<= 1) {
            s0  += __shfl_xor_sync(0xffffffffu, s0,  o);
            ss0 += __shfl_xor_sync(0xffffffffu, ss0, o);
            s1  += __shfl_xor_sync(0xffffffffu, s1,  o);
            ss1 += __shfl_xor_sync(0xffffffffu, ss1, o);
        }
        const int r0 = wrow + mt * 16 + g, r1 = r0 + 8;
        const float mean0 = s0 * (1.0f / HD);
        const float mean1 = s1 * (1.0f / HD);
        const float rstd0 = rsqrtf(ss0 * (1.0f / HD) - mean0 * mean0 + LN_EPS);
        const float rstd1 = rsqrtf(ss1 * (1.0f / HD) - mean1 * mean1 + LN_EPS);
        const float mv0 = mrow ? (float)mrow[r0] : 1.0f;
        const float mv1 = mrow ? (float)mrow[r1] : 1.0f;
#pragma unroll
        for (int kk = 0; kk < 8; kk++) {
            const int nta = 2 * kk, ntb = 2 * kk + 1;
            const float2 lwa = *(const float2*)(sLW + nta * 8 + 2 * q4);
            const float2 lba = *(const float2*)(sLB + nta * 8 + 2 * q4);
            const float2 lwb = *(const float2*)(sLW + ntb * 8 + 2 * q4);
            const float2 lbb = *(const float2*)(sLB + ntb * 8 + 2 * q4);
            float y00 = ((acc[mt][nta][0] - mean0) * rstd0 * lwa.x + lba.x) * mv0;
            float y01 = ((acc[mt][nta][1] - mean0) * rstd0 * lwa.y + lba.y) * mv0;
            float y10 = ((acc[mt][nta][2] - mean1) * rstd1 * lwa.x + lba.x) * mv1;
            float y11 = ((acc[mt][nta][3] - mean1) * rstd1 * lwa.y + lba.y) * mv1;
            float y20 = ((acc[mt][ntb][0] - mean0) * rstd0 * lwb.x + lbb.x) * mv0;
            float y21 = ((acc[mt][ntb][1] - mean0) * rstd0 * lwb.y + lbb.y) * mv0;
            float y30 = ((acc[mt][ntb][2] - mean1) * rstd1 * lwb.x + lbb.x) * mv1;
            float y31 = ((acc[mt][ntb][3] - mean1) * rstd1 * lwb.y + lbb.y) * mv1;
            ah[mt][kk][0] = pack2(y00, y01);
            ah[mt][kk][1] = pack2(y10, y11);
            ah[mt][kk][2] = pack2(y20, y21);
            ah[mt][kk][3] = pack2(y30, y31);
            if (store_x) {
                *(uint32_t*)(smem + ESM_X + swz(r0, nta) + 4 * q4) = ah[mt][kk][0];
                *(uint32_t*)(smem + ESM_X + swz(r1, nta) + 4 * q4) = ah[mt][kk][1];
                *(uint32_t*)(smem + ESM_X + swz(r0, ntb) + 4 * q4) = ah[mt][kk][2];
                *(uint32_t*)(smem + ESM_X + swz(r1, ntb) + 4 * q4) = ah[mt][kk][3];
            }
        }
    }
    __syncwarp();
}

template <int ISQ>
__global__ __launch_bounds__(128, 2)
void encode_fused(const int* __restrict__ ids, const int* __restrict__ mask,
                  const float* __restrict__ emb,
                  const float* __restrict__ b1, const float* __restrict__ b2,
                  const float* __restrict__ lnw, const float* __restrict__ lnb,
                  const int* __restrict__ dmask, int mat0)
{
    extern __shared__ __align__(16) char smem[];
    const int tid = threadIdx.x, wid = tid >> 5, lane = tid & 31;
    const uint32_t sb = smem_u32(smem);
    float* sP = (float*)(smem + ESM_P);

    sP[tid]       = b1[tid];
    sP[128 + tid] = b2[tid];
    sP[256 + tid] = lnw[tid];
    sP[384 + tid] = lnb[tid];

    // W1 -> WA, W2 -> WB (swizzled)
    {
        const uint4* w1 = (const uint4*)g_wt[mat0];
        const uint4* w2 = (const uint4*)g_wt[mat0 + 1];
#pragma unroll
        for (int i = 0; i < 16; i++) {
            int idx = tid + i * 128;       // 2048 chunks
            int r = idx >> 4, c = idx & 15;
            *(uint4*)(smem + ESM_WA + swz(r, c)) = w1[idx];
            *(uint4*)(smem + ESM_WB + swz(r, c)) = w2[idx];
        }
    }

    // embedding gather: 1 thread per token
    {
        const int id = ids[(size_t)blockIdx.x * 128 + tid];
        const float4* er = (const float4*)(emb + (size_t)id * HD);
#pragma unroll
        for (int c = 0; c < 16; c++) {
            float4 fa = er[2 * c], fb = er[2 * c + 1];
            *(uint4*)(smem + ESM_X + swz(tid, c)) =
                make_uint4(pack2(fa.x, fa.y), pack2(fa.z, fa.w),
                           pack2(fb.x, fb.y), pack2(fb.z, fb.w));
        }
    }
    __syncthreads();

    const int wrow = wid * 32;
    float acc[2][16][4];
    uint32_t ah[2][8][4];

    // ---- layer 1 ----
    init_bias(acc, sP, lane & 3);
    mma_A_smem(acc, sb + ESM_X, sb + ESM_WA, lane, wrow);
    epilogue(acc, ah, sP + 256, sP + 384, lane, wrow, nullptr, smem, 1);
    __syncthreads();   // all warps done reading WA (W1); X(layer-1) complete

    // prefetch Q tile into registers (doc path) — hidden behind layer-2 MMAs
    uint4 qreg[8];
    if (!ISQ) {
        const int b = blockIdx.x >> 5;
        const uint4* qs = (const uint4*)(g_qv + (size_t)b * LQ * HD);
#pragma unroll
        for (int i = 0; i < 8; i++) qreg[i] = qs[tid + i * 128];
    }

    // ---- layer 2 (A from SMEM X — proven R5 path) ----
    init_bias(acc, sP + 128, lane & 3);
    mma_A_smem(acc, sb + ESM_X, sb + ESM_WB, lane, wrow);
    epilogue(acc, ah, sP + 256, sP + 384, lane, wrow,
             ISQ ? (mask + (size_t)blockIdx.x * 128) : nullptr, smem, ISQ);

    if (ISQ) {
        __syncthreads();
        uint4* gdst = (uint4*)g_qv + (size_t)blockIdx.x * 2048;
#pragma unroll
        for (int i = 0; i < 16; i++)
            gdst[tid + i * 128] = ((const uint4*)(smem + ESM_X))[tid + i * 128];
        return;
    }

    // stage prefetched Q tile into WA, then sim
#pragma unroll
    for (int i = 0; i < 8; i++)
        ((uint4*)(smem + ESM_WA))[tid + i * 128] = qreg[i];
    __syncthreads();

    // ---- fused maxsim: D[128 docs] x Q[64 queries], K=128, A from regs ----
    float sa[2][8][4];
#pragma unroll
    for (int mt = 0; mt < 2; mt++)
#pragma unroll
        for (int nt = 0; nt < 8; nt++) {
            sa[mt][nt][0] = 0.f; sa[mt][nt][1] = 0.f;
            sa[mt][nt][2] = 0.f; sa[mt][nt][3] = 0.f;
        }
    {
        const int brow0 = (lane & 7) + ((lane >> 4) & 1) * 8;
        const int bkc   = (lane >> 3) & 1;
#pragma unroll
        for (int kk = 0; kk < 8; kk++) {
            uint32_t bc_[2][4];
            ldsm_x4(bc_[0][0], bc_[0][1], bc_[0][2], bc_[0][3],
                    sb + ESM_WA + swz(brow0, kk * 2 + bkc));
#pragma unroll
            for (int nt2 = 0; nt2 < 4; nt2++) {
                const int cur = nt2 & 1, nxt = cur ^ 1;
                if (nt2 < 3)
                    ldsm_x4(bc_[nxt][0], bc_[nxt][1], bc_[nxt][2], bc_[nxt][3],
                            sb + ESM_WA + swz((nt2 + 1) * 16 + brow0, kk * 2 + bkc));
                mma16816(sa[0][2 * nt2],     ah[0][kk][0], ah[0][kk][1],
                         ah[0][kk][2], ah[0][kk][3], bc_[cur][0], bc_[cur][1]);
                mma16816(sa[0][2 * nt2 + 1], ah[0][kk][0], ah[0][kk][1],
                         ah[0][kk][2], ah[0][kk][3], bc_[cur][2], bc_[cur][3]);
                mma16816(sa[1][2 * nt2],     ah[1][kk][0], ah[1][kk][1],
                         ah[1][kk][2], ah[1][kk][3], bc_[cur][0], bc_[cur][1]);
                mma16816(sa[1][2 * nt2 + 1], ah[1][kk][0], ah[1][kk][1],
                         ah[1][kk][2], ah[1][kk][3], bc_[cur][2], bc_[cur][3]);
            }
        }
    }

    // penalties + max over this warp's 32 doc rows
    const int g = lane >> 2;
    int r4[4] = {wrow + g, wrow + g + 8, wrow + 16 + g, wrow + 24 + g};
    float p[4];
#pragma unroll
    for (int j = 0; j < 4; j++)
        p[j] = (1.0f - (float)dmask[(size_t)blockIdx.x * 128 + r4[j]]) * NEGV;

    float* red = (float*)(smem + ESM_RED);
#pragma unroll
    for (int nt = 0; nt < 8; nt++) {
        float v0 = -3.0e38f, v1 = -3.0e38f;
#pragma unroll
        for (int j = 0; j < 4; j++) {
            const int mt = j >> 1, h = j & 1;
            v0 = fmaxf(v0, sa[mt][nt][2 * h]     + p[j]);
            v1 = fmaxf(v1, sa[mt][nt][2 * h + 1] + p[j]);
        }
#pragma unroll
        for (int o = 4; o <= 16; o <<= 1) {
            v0 = fmaxf(v0, __shfl_xor_sync(0xffffffffu, v0, o));
            v1 = fmaxf(v1, __shfl_xor_sync(0xffffffffu, v1, o));
        }
        if (lane < 4)
            *(float2*)(red + wid * 64 + nt * 8 + 2 * lane) = make_float2(v0, v1);
    }
    __syncthreads();
    if (tid < 64) {
        float m = red[tid];
#pragma unroll
        for (int w = 1; w < 4; w++) m = fmaxf(m, red[w * 64 + tid]);
        g_pmax[(size_t)blockIdx.x * 64 + tid] = m;
    }
}

// ---------------- final: max over tiles, sum over queries ------------------
__global__ void final_k(float* __restrict__ out)
{
    const int b = blockIdx.x, tid = threadIdx.x;    // 256 threads
    const int q = tid & 63, part = tid >> 6;        // 4 parts x 8 tiles
    float m = -3.0e38f;
#pragma unroll
    for (int t = 0; t < 8; t++)
        m = fmaxf(m, g_pmax[(size_t)b * (NTILE * LQ) + (part * 8 + t) * LQ + q]);
    __shared__ float red[256];
    red[tid] = m;
    __syncthreads();
    if (tid < 64) {
        float s = fmaxf(fmaxf(red[tid], red[tid + 64]),
                        fmaxf(red[tid + 128], red[tid + 192]));
#pragma unroll
        for (int o = 16; o > 0; o >>= 1)
            s += __shfl_xor_sync(0xffffffffu, s, o);
        if ((tid & 31) == 0) red[tid >> 5] = s;
    }
    __syncthreads();
    if (tid == 0) out[b] = red[0] + red[1];
}

// ---------------- launch ---------------------------------------------------
extern "C" void kernel_launch(void* const* d_in, const int* in_sizes, int n_in,
                              void* d_out, int out_size)
{
    const int*   qids  = (const int*)d_in[0];
    const int*   dids  = (const int*)d_in[1];
    const int*   qmask = (const int*)d_in[2];
    const int*   dmask = (const int*)d_in[3];
    const float* q_emb = (const float*)d_in[4];
    const float* qW1   = (const float*)d_in[5];
    const float* qb1   = (const float*)d_in[6];
    const float* qW2   = (const float*)d_in[7];
    const float* qb2   = (const float*)d_in[8];
    const float* q_lnw = (const float*)d_in[9];
    const float* q_lnb = (const float*)d_in[10];
    const float* d_emb = (const float*)d_in[11];
    const float* dW1   = (const float*)d_in[12];
    const float* db1   = (const float*)d_in[13];
    const float* dW2   = (const float*)d_in[14];
    const float* db2   = (const float*)d_in[15];
    const float* d_lnw = (const float*)d_in[16];
    const float* d_lnb = (const float*)d_in[17];
    float* out = (float*)d_out;

    cudaFuncSetAttribute(encode_fused<0>,
        cudaFuncAttributeMaxDynamicSharedMemorySize, ESM_TOTAL);
    cudaFuncSetAttribute(encode_fused<1>,
        cudaFuncAttributeMaxDynamicSharedMemorySize, ESM_TOTAL);

    prep_kernel<<<256, 256>>>(dW1, dW2, qW1, qW2);

    // queries first (writes g_qv, swizzled)
    encode_fused<1><<<(BB * LQ) / 128, 128, ESM_TOTAL>>>(
        qids, qmask, q_emb, qb1, qb2, q_lnw, q_lnb, dmask, 2);
    // docs with fused maxsim (reads g_qv, writes g_pmax)
    encode_fused<0><<<(BB * LDOC) / 128, 128, ESM_TOTAL>>>(
        dids, dmask, d_emb, db1, db2, d_lnw, d_lnb, dmask, 0);

    final_k<<<BB, 256>>>(out);
}

// round 11
// speedup vs baseline: 1.4165x; 1.0182x over previous
#include <cuda_runtime.h>
#include <cuda_fp16.h>
#include <stdint.h>

#define HD    128
#define BB    64
#define LQ    64
#define LDOC  4096
#define NTILE 32               // 4096/128 doc tiles per batch
#define LN_EPS 1e-5f
#define NEGV  -1e30f

// ---------------- scratch (__device__ globals; no cudaMalloc) --------------
__device__ __half g_wt[4][HD * HD];                 // transposed fp16 weights
__device__ __half g_qv[(size_t)BB * LQ * HD];       // 1 MB, stored SWIZZLED
__device__ float  g_pmax[(size_t)BB * NTILE * LQ];  // 512 KB

// ---------------- helpers ---------------------------------------------------
__device__ __forceinline__ uint32_t smem_u32(const void* p) {
    uint32_t a;
    asm("{ .reg .u64 t; cvta.to.shared.u64 t, %1; cvt.u32.u64 %0, t; }"
        : "=r"(a) : "l"(p));
    return a;
}

__device__ __forceinline__ void ldsm_x4(uint32_t& r0, uint32_t& r1,
                                        uint32_t& r2, uint32_t& r3, uint32_t a) {
    asm volatile("ldmatrix.sync.aligned.m8n8.x4.shared.b16 {%0,%1,%2,%3}, [%4];"
                 : "=r"(r0), "=r"(r1), "=r"(r2), "=r"(r3) : "r"(a));
}

__device__ __forceinline__ void mma16816(float* c,
                                         uint32_t a0, uint32_t a1, uint32_t a2,
                                         uint32_t a3, uint32_t b0, uint32_t b1) {
    asm volatile(
        "mma.sync.aligned.m16n8k16.row.col.f32.f16.f16.f32 "
        "{%0,%1,%2,%3}, {%4,%5,%6,%7}, {%8,%9}, {%0,%1,%2,%3};"
        : "+f"(c[0]), "+f"(c[1]), "+f"(c[2]), "+f"(c[3])
        : "r"(a0), "r"(a1), "r"(a2), "r"(a3), "r"(b0), "r"(b1));
}

__device__ __forceinline__ uint32_t pack2(float a, float b) {
    __half2 h = __floats2half2_rn(a, b);
    return *(uint32_t*)&h;
}

// swizzled smem offset for (row, 16B-chunk) in a [rows][256B] fp16 tile
__device__ __forceinline__ uint32_t swz(int row, int chunk) {
    return (uint32_t)(row * 256 + ((chunk ^ (row & 7)) * 16));
}

// ---------------- prep: transpose + fp16 convert of the 4 weights ----------
__global__ void prep_kernel(const float* __restrict__ dW1,
                            const float* __restrict__ dW2,
                            const float* __restrict__ qW1,
                            const float* __restrict__ qW2) {
    int i = blockIdx.x * blockDim.x + threadIdx.x;   // 65536 total
    const float* Ws[4] = {dW1, dW2, qW1, qW2};
    int mat = i >> 14, r = i & 16383, j = r >> 7, k = r & 127;
    g_wt[mat][j * HD + k] = __float2half_rn(Ws[mat][k * HD + j]);
}

// ---------------- fused encode (+maxsim for docs) --------------------------
// 128 threads = 4 warps, M=32 token rows per warp. ONE weight buffer
// (reloaded between stages) -> 68 KB SMEM -> 3 CTAs/SM.
#define ESM_X   0
#define ESM_W   32768
#define ESM_P   65536
#define ESM_RED 67584
#define ESM_TOTAL 68608

__device__ __forceinline__ void init_bias(float (&acc)[2][16][4],
                                          const float* __restrict__ sB, int q4) {
#pragma unroll
    for (int nt = 0; nt < 16; nt++) {
        const float2 bc = *(const float2*)(sB + nt * 8 + 2 * q4);
#pragma unroll
        for (int mt = 0; mt < 2; mt++) {
            acc[mt][nt][0] = bc.x; acc[mt][nt][1] = bc.y;
            acc[mt][nt][2] = bc.x; acc[mt][nt][3] = bc.y;
        }
    }
}

// A from SMEM tile Xb, B double-buffered from Wb
__device__ __forceinline__ void mma_A_smem(float (&acc)[2][16][4],
                                           uint32_t Xb, uint32_t Wb,
                                           int lane, int wrow) {
    const int arow  = wrow + (lane & 7) + ((lane >> 3) & 1) * 8;
    const int akc   = (lane >> 4) & 1;
    const int brow0 = (lane & 7) + ((lane >> 4) & 1) * 8;
    const int bkc   = (lane >> 3) & 1;
#pragma unroll
    for (int kk = 0; kk < 8; kk++) {
        uint32_t a0[4], a1[4];
        ldsm_x4(a0[0], a0[1], a0[2], a0[3], Xb + swz(arow,      kk * 2 + akc));
        ldsm_x4(a1[0], a1[1], a1[2], a1[3], Xb + swz(arow + 16, kk * 2 + akc));
        uint32_t bc_[2][4];
        ldsm_x4(bc_[0][0], bc_[0][1], bc_[0][2], bc_[0][3],
                Wb + swz(brow0, kk * 2 + bkc));
#pragma unroll
        for (int nt2 = 0; nt2 < 8; nt2++) {
            const int cur = nt2 & 1, nxt = cur ^ 1;
            if (nt2 < 7)
                ldsm_x4(bc_[nxt][0], bc_[nxt][1], bc_[nxt][2], bc_[nxt][3],
                        Wb + swz((nt2 + 1) * 16 + brow0, kk * 2 + bkc));
            mma16816(acc[0][2 * nt2],     a0[0], a0[1], a0[2], a0[3],
                     bc_[cur][0], bc_[cur][1]);
            mma16816(acc[0][2 * nt2 + 1], a0[0], a0[1], a0[2], a0[3],
                     bc_[cur][2], bc_[cur][3]);
            mma16816(acc[1][2 * nt2],     a1[0], a1[1], a1[2], a1[3],
                     bc_[cur][0], bc_[cur][1]);
            mma16816(acc[1][2 * nt2 + 1], a1[0], a1[1], a1[2], a1[3],
                     bc_[cur][2], bc_[cur][3]);
        }
    }
}

// ReLU + LayerNorm (+opt mask); result written to SMEM X as fp16
__device__ __forceinline__ void epilogue(float (&acc)[2][16][4],
                                         const float* __restrict__ sLW,
                                         const float* __restrict__ sLB,
                                         int lane, int wrow,
                                         const int* __restrict__ mrow,
                                         char* __restrict__ smem) {
    const int g = lane >> 2, q4 = lane & 3;
#pragma unroll
    for (int mt = 0; mt < 2; mt++) {
        float s0 = 0.f, ss0 = 0.f, s1 = 0.f, ss1 = 0.f;
#pragma unroll
        for (int nt = 0; nt < 16; nt++) {
            float v0 = fmaxf(acc[mt][nt][0], 0.f);
            float v1 = fmaxf(acc[mt][nt][1], 0.f);
            float v2 = fmaxf(acc[mt][nt][2], 0.f);
            float v3 = fmaxf(acc[mt][nt][3], 0.f);
            acc[mt][nt][0] = v0; acc[mt][nt][1] = v1;
            acc[mt][nt][2] = v2; acc[mt][nt][3] = v3;
            s0 += v0 + v1; ss0 += v0 * v0 + v1 * v1;
            s1 += v2 + v3; ss1 += v2 * v2 + v3 * v3;
        }
#pragma unroll
        for (int o = 1; o <= 2; o <<= 1) {
            s0  += __shfl_xor_sync(0xffffffffu, s0,  o);
            ss0 += __shfl_xor_sync(0xffffffffu, ss0, o);
            s1  += __shfl_xor_sync(0xffffffffu, s1,  o);
            ss1 += __shfl_xor_sync(0xffffffffu, ss1, o);
        }
        const int r0 = wrow + mt * 16 + g, r1 = r0 + 8;
        const float mean0 = s0 * (1.0f / HD);
        const float mean1 = s1 * (1.0f / HD);
        const float rstd0 = rsqrtf(ss0 * (1.0f / HD) - mean0 * mean0 + LN_EPS);
        const float rstd1 = rsqrtf(ss1 * (1.0f / HD) - mean1 * mean1 + LN_EPS);
        const float mv0 = mrow ? (float)mrow[r0] : 1.0f;
        const float mv1 = mrow ? (float)mrow[r1] : 1.0f;
#pragma unroll
        for (int nt = 0; nt < 16; nt++) {
            const float2 lw = *(const float2*)(sLW + nt * 8 + 2 * q4);
            const float2 lb = *(const float2*)(sLB + nt * 8 + 2 * q4);
            float y0 = ((acc[mt][nt][0] - mean0) * rstd0 * lw.x + lb.x) * mv0;
            float y1 = ((acc[mt][nt][1] - mean0) * rstd0 * lw.y + lb.y) * mv0;
            float y2 = ((acc[mt][nt][2] - mean1) * rstd1 * lw.x + lb.x) * mv1;
            float y3 = ((acc[mt][nt][3] - mean1) * rstd1 * lw.y + lb.y) * mv1;
            *(uint32_t*)(smem + ESM_X + swz(r0, nt) + 4 * q4) = pack2(y0, y1);
            *(uint32_t*)(smem + ESM_X + swz(r1, nt) + 4 * q4) = pack2(y2, y3);
        }
    }
    __syncwarp();
}

__device__ __forceinline__ void load_w(char* __restrict__ smem,
                                       const __half* __restrict__ src, int tid) {
    const uint4* w = (const uint4*)src;
#pragma unroll
    for (int i = 0; i < 16; i++) {
        int idx = tid + i * 128;       // 2048 chunks
        int r = idx >> 4, c = idx & 15;
        *(uint4*)(smem + ESM_W + swz(r, c)) = w[idx];
    }
}

template <int ISQ>
__global__ __launch_bounds__(128, 3)
void encode_fused(const int* __restrict__ ids, const int* __restrict__ mask,
                  const float* __restrict__ emb,
                  const float* __restrict__ b1, const float* __restrict__ b2,
                  const float* __restrict__ lnw, const float* __restrict__ lnb,
                  const int* __restrict__ dmask, int mat0)
{
    extern __shared__ __align__(16) char smem[];
    const int tid = threadIdx.x, wid = tid >> 5, lane = tid & 31;
    const uint32_t sb = smem_u32(smem);
    float* sP = (float*)(smem + ESM_P);

    sP[tid]       = b1[tid];
    sP[128 + tid] = b2[tid];
    sP[256 + tid] = lnw[tid];
    sP[384 + tid] = lnb[tid];

    load_w(smem, g_wt[mat0], tid);

    // embedding gather: 1 thread per token
    {
        const int id = ids[(size_t)blockIdx.x * 128 + tid];
        const float4* er = (const float4*)(emb + (size_t)id * HD);
#pragma unroll
        for (int c = 0; c < 16; c++) {
            float4 fa = er[2 * c], fb = er[2 * c + 1];
            *(uint4*)(smem + ESM_X + swz(tid, c)) =
                make_uint4(pack2(fa.x, fa.y), pack2(fa.z, fa.w),
                           pack2(fb.x, fb.y), pack2(fb.z, fb.w));
        }
    }
    __syncthreads();

    const int wrow = wid * 32;
    float acc[2][16][4];

    // ---- layer 1 ----
    init_bias(acc, sP, lane & 3);
    mma_A_smem(acc, sb + ESM_X, sb + ESM_W, lane, wrow);
    epilogue(acc, sP + 256, sP + 384, lane, wrow, nullptr, smem);
    __syncthreads();           // all warps done reading W (=W1)

    load_w(smem, g_wt[mat0 + 1], tid);   // W <- W2
    __syncthreads();

    // ---- layer 2 ----
    init_bias(acc, sP + 128, lane & 3);
    mma_A_smem(acc, sb + ESM_X, sb + ESM_W, lane, wrow);
    epilogue(acc, sP + 256, sP + 384, lane, wrow,
             ISQ ? (mask + (size_t)blockIdx.x * 128) : nullptr, smem);

    if (ISQ) {
        __syncthreads();
        uint4* gdst = (uint4*)g_qv + (size_t)blockIdx.x * 2048;
#pragma unroll
        for (int i = 0; i < 16; i++)
            gdst[tid + i * 128] = ((const uint4*)(smem + ESM_X))[tid + i * 128];
        return;
    }

    __syncthreads();           // all warps done reading W (=W2)
    // stage this batch's query tile (already swizzled in g_qv) into W
    {
        const int b = blockIdx.x >> 5;
        const uint4* qs = (const uint4*)(g_qv + (size_t)b * LQ * HD);
#pragma unroll
        for (int i = 0; i < 8; i++)
            ((uint4*)(smem + ESM_W))[tid + i * 128] = qs[tid + i * 128];
    }
    __syncthreads();

    // ---- fused maxsim: D[128 docs] x Q[64 queries], K=128 ----
    float sa[2][8][4];
#pragma unroll
    for (int mt = 0; mt < 2; mt++)
#pragma unroll
        for (int nt = 0; nt < 8; nt++) {
            sa[mt][nt][0] = 0.f; sa[mt][nt][1] = 0.f;
            sa[mt][nt][2] = 0.f; sa[mt][nt][3] = 0.f;
        }
    {
        const int arow  = wrow + (lane & 7) + ((lane >> 3) & 1) * 8;
        const int akc   = (lane >> 4) & 1;
        const int brow0 = (lane & 7) + ((lane >> 4) & 1) * 8;
        const int bkc   = (lane >> 3) & 1;
#pragma unroll
        for (int kk = 0; kk < 8; kk++) {
            uint32_t a0[4], a1[4];
            ldsm_x4(a0[0], a0[1], a0[2], a0[3],
                    sb + ESM_X + swz(arow,      kk * 2 + akc));
            ldsm_x4(a1[0], a1[1], a1[2], a1[3],
                    sb + ESM_X + swz(arow + 16, kk * 2 + akc));
            uint32_t bc_[2][4];
            ldsm_x4(bc_[0][0], bc_[0][1], bc_[0][2], bc_[0][3],
                    sb + ESM_W + swz(brow0, kk * 2 + bkc));
#pragma unroll
            for (int nt2 = 0; nt2 < 4; nt2++) {
                const int cur = nt2 & 1, nxt = cur ^ 1;
                if (nt2 < 3)
                    ldsm_x4(bc_[nxt][0], bc_[nxt][1], bc_[nxt][2], bc_[nxt][3],
                            sb + ESM_W + swz((nt2 + 1) * 16 + brow0, kk * 2 + bkc));
                mma16816(sa[0][2 * nt2],     a0[0], a0[1], a0[2], a0[3],
                         bc_[cur][0], bc_[cur][1]);
                mma16816(sa[0][2 * nt2 + 1], a0[0], a0[1], a0[2], a0[3],
                         bc_[cur][2], bc_[cur][3]);
                mma16816(sa[1][2 * nt2],     a1[0], a1[1], a1[2], a1[3],
                         bc_[cur][0], bc_[cur][1]);
                mma16816(sa[1][2 * nt2 + 1], a1[0], a1[1], a1[2], a1[3],
                         bc_[cur][2], bc_[cur][3]);
            }
        }
    }

    // penalties + max over this warp's 32 doc rows
    const int g = lane >> 2;
    int r4[4] = {wrow + g, wrow + g + 8, wrow + 16 + g, wrow + 24 + g};
    float p[4];
#pragma unroll
    for (int j = 0; j < 4; j++)
        p[j] = (1.0f - (float)dmask[(size_t)blockIdx.x * 128 + r4[j]]) * NEGV;

    float* red = (float*)(smem + ESM_RED);
#pragma unroll
    for (int nt = 0; nt < 8; nt++) {
        float v0 = -3.0e38f, v1 = -3.0e38f;
#pragma unroll
        for (int j = 0; j < 4; j++) {
            const int mt = j >> 1, h = j & 1;
            v0 = fmaxf(v0, sa[mt][nt][2 * h]     + p[j]);
            v1 = fmaxf(v1, sa[mt][nt][2 * h + 1] + p[j]);
        }
#pragma unroll
        for (int o = 4; o <= 16; o <<= 1) {
            v0 = fmaxf(v0, __shfl_xor_sync(0xffffffffu, v0, o));
            v1 = fmaxf(v1, __shfl_xor_sync(0xffffffffu, v1, o));
        }
        if (lane < 4)
            *(float2*)(red + wid * 64 + nt * 8 + 2 * lane) = make_float2(v0, v1);
    }
    __syncthreads();
    if (tid < 64) {
        float m = red[tid];
#pragma unroll
        for (int w = 1; w < 4; w++) m = fmaxf(m, red[w * 64 + tid]);
        g_pmax[(size_t)blockIdx.x * 64 + tid] = m;
    }
}

// ---------------- final: max over tiles, sum over queries ------------------
__global__ void final_k(float* __restrict__ out)
{
    const int b = blockIdx.x, tid = threadIdx.x;    // 256 threads
    const int q = tid & 63, part = tid >> 6;        // 4 parts x 8 tiles
    float m = -3.0e38f;
#pragma unroll
    for (int t = 0; t < 8; t++)
        m = fmaxf(m, g_pmax[(size_t)b * (NTILE * LQ) + (part * 8 + t) * LQ + q]);
    __shared__ float red[256];
    red[tid] = m;
    __syncthreads();
    if (tid < 64) {
        float s = fmaxf(fmaxf(red[tid], red[tid + 64]),
                        fmaxf(red[tid + 128], red[tid + 192]));
#pragma unroll
        for (int o = 16; o > 0; o >>= 1)
            s += __shfl_xor_sync(0xffffffffu, s, o);
        if ((tid & 31) == 0) red[tid >> 5] = s;
    }
    __syncthreads();
    if (tid == 0) out[b] = red[0] + red[1];
}

// ---------------- launch ---------------------------------------------------
extern "C" void kernel_launch(void* const* d_in, const int* in_sizes, int n_in,
                              void* d_out, int out_size)
{
    const int*   qids  = (const int*)d_in[0];
    const int*   dids  = (const int*)d_in[1];
    const int*   qmask = (const int*)d_in[2];
    const int*   dmask = (const int*)d_in[3];
    const float* q_emb = (const float*)d_in[4];
    const float* qW1   = (const float*)d_in[5];
    const float* qb1   = (const float*)d_in[6];
    const float* qW2   = (const float*)d_in[7];
    const float* qb2   = (const float*)d_in[8];
    const float* q_lnw = (const float*)d_in[9];
    const float* q_lnb = (const float*)d_in[10];
    const float* d_emb = (const float*)d_in[11];
    const float* dW1   = (const float*)d_in[12];
    const float* db1   = (const float*)d_in[13];
    const float* dW2   = (const float*)d_in[14];
    const float* db2   = (const float*)d_in[15];
    const float* d_lnw = (const float*)d_in[16];
    const float* d_lnb = (const float*)d_in[17];
    float* out = (float*)d_out;

    cudaFuncSetAttribute(encode_fused<0>,
        cudaFuncAttributeMaxDynamicSharedMemorySize, ESM_TOTAL);
    cudaFuncSetAttribute(encode_fused<1>,
        cudaFuncAttributeMaxDynamicSharedMemorySize, ESM_TOTAL);

    prep_kernel<<<256, 256>>>(dW1, dW2, qW1, qW2);

    // queries first (writes g_qv, swizzled)
    encode_fused<1><<<(BB * LQ) / 128, 128, ESM_TOTAL>>>(
        qids, qmask, q_emb, qb1, qb2, q_lnw, q_lnb, dmask, 2);
    // docs with fused maxsim (reads g_qv, writes g_pmax)
    encode_fused<0><<<(BB * LDOC) / 128, 128, ESM_TOTAL>>>(
        dids, dmask, d_emb, db1, db2, d_lnw, d_lnb, dmask, 0);

    final_k<<<BB, 256>>>(out);
}